// round 1
// baseline (speedup 1.0000x reference)
#include <cuda_runtime.h>

// Problem constants (fixed shapes per reference)
#define B_  4
#define C_  256
#define H_  128
#define W_  128
#define OH_ 256
#define OW_ 256
#define OFFSET_FACTOR 0.70710678118654752440f   // sqrt(128/256)

// Scratch: per-output-pixel bilinear metadata (shared across all 256 channels)
__device__ float4 g_meta_w[B_ * OH_ * OW_];   // 4 MB: bilinear weights
__device__ int    g_meta_idx[B_ * OH_ * OW_]; // 1 MB: packed x0|x1<<7|y0<<14|y1<<21

// ---------------------------------------------------------------------------
// Kernel 1: 1x1 conv -> offsets -> bilinear metadata
// grid (H_, B_), block 128 (one thread per w)
// ---------------------------------------------------------------------------
__global__ void offsets_kernel(const float* __restrict__ x,
                               const float* __restrict__ cw,   // [8][256]
                               const float* __restrict__ cb) { // [8]
    __shared__ float sw[256 * 8];  // transposed: [c][o] so we can LDS.128
    const int tid = threadIdx.x;
    for (int i = tid; i < 2048; i += 128) {
        int o = i >> 8, c = i & 255;
        sw[c * 8 + o] = cw[i];
    }
    __syncthreads();

    const int h = blockIdx.x;
    const int b = blockIdx.y;
    const int w = tid;

    float acc[8];
#pragma unroll
    for (int o = 0; o < 8; o++) acc[o] = cb[o];

    const float* xp = x + (((long)b * C_) * H_ + h) * W_ + w;
#pragma unroll 4
    for (int c = 0; c < C_; c++) {
        float v = __ldg(xp + (long)c * (H_ * W_));
        float4 wa = *reinterpret_cast<const float4*>(&sw[c * 8]);
        float4 wb = *reinterpret_cast<const float4*>(&sw[c * 8 + 4]);
        acc[0] += wa.x * v; acc[1] += wa.y * v;
        acc[2] += wa.z * v; acc[3] += wa.w * v;
        acc[4] += wb.x * v; acc[5] += wb.y * v;
        acc[6] += wb.z * v; acc[7] += wb.w * v;
    }

#pragma unroll
    for (int k = 0; k < 4; k++) {
        int sy = k >> 1, sx = k & 1;
        float xc = OFFSET_FACTOR * acc[k]     + (float)w + 0.5f * (float)sx;
        float yc = OFFSET_FACTOR * acc[4 + k] + (float)h + 0.5f * (float)sy;
        float x0f = floorf(xc), y0f = floorf(yc);
        float fx = xc - x0f,   fy = yc - y0f;
        int x0 = min(max((int)x0f, 0), W_ - 1);
        int x1 = min(max((int)x0f + 1, 0), W_ - 1);
        int y0 = min(max((int)y0f, 0), H_ - 1);
        int y1 = min(max((int)y0f + 1, 0), H_ - 1);

        float4 w4 = make_float4((1.f - fx) * (1.f - fy),
                                fx * (1.f - fy),
                                (1.f - fx) * fy,
                                fx * fy);
        int pk = x0 | (x1 << 7) | (y0 << 14) | (y1 << 21);

        int oh = 2 * h + sy, ow = 2 * w + sx;
        int midx = (b * OH_ + oh) * OW_ + ow;
        g_meta_w[midx] = w4;
        g_meta_idx[midx] = pk;
    }
}

// ---------------------------------------------------------------------------
// Kernel 2: bilinear gather
// block = 256 threads; each block: 32x32 output tile x 16 channels
// grid (OW_/32, OH_/32, B_ * (C_/16)) = (8, 8, 64)
// ---------------------------------------------------------------------------
#define CH_PER 16

__global__ __launch_bounds__(256) void gather_kernel(const float* __restrict__ x,
                                                     float* __restrict__ out) {
    const int tid = threadIdx.x;
    const int bz = blockIdx.z;
    const int b  = bz >> 4;
    const int c0 = (bz & 15) * CH_PER;
    const int oh_base = blockIdx.y * 32;
    const int ow_base = blockIdx.x * 32;

    // Per-thread metadata for 4 pixels, held in registers across the channel loop
    float4 w4[4];
    int o00[4], o01[4], o10[4], o11[4], outoff[4];
#pragma unroll
    for (int j = 0; j < 4; j++) {
        int p  = tid + j * 256;
        int oh = oh_base + (p >> 5);
        int ow = ow_base + (p & 31);
        int midx = (b * OH_ + oh) * OW_ + ow;
        w4[j] = g_meta_w[midx];
        int pk = g_meta_idx[midx];
        int x0 =  pk        & 127;
        int x1 = (pk >> 7)  & 127;
        int y0 = (pk >> 14) & 127;
        int y1 = (pk >> 21) & 127;
        o00[j] = y0 * W_ + x0;
        o01[j] = y0 * W_ + x1;
        o10[j] = y1 * W_ + x0;
        o11[j] = y1 * W_ + x1;
        outoff[j] = oh * OW_ + ow;
    }

    const float* plane = x   + ((long)(b * C_ + c0) * (H_ * W_));
    float*       outp  = out + ((long)(b * C_ + c0) * (OH_ * OW_));

    for (int cc = 0; cc < CH_PER; cc++) {
#pragma unroll
        for (int j = 0; j < 4; j++) {
            float v = w4[j].x * __ldg(plane + o00[j])
                    + w4[j].y * __ldg(plane + o01[j])
                    + w4[j].z * __ldg(plane + o10[j])
                    + w4[j].w * __ldg(plane + o11[j]);
            outp[outoff[j]] = v;
        }
        plane += H_ * W_;
        outp  += OH_ * OW_;
    }
}

// ---------------------------------------------------------------------------
extern "C" void kernel_launch(void* const* d_in, const int* in_sizes, int n_in,
                              void* d_out, int out_size) {
    const float* x  = (const float*)d_in[0];  // (4,256,128,128)
    const float* cw = (const float*)d_in[1];  // (8,256,1,1)
    const float* cb = (const float*)d_in[2];  // (8,)
    float* out = (float*)d_out;               // (4,256,256,256)

    offsets_kernel<<<dim3(H_, B_), 128>>>(x, cw, cb);
    gather_kernel<<<dim3(OW_ / 32, OH_ / 32, B_ * (C_ / CH_PER)), 256>>>(x, out);
}

// round 2
// speedup vs baseline: 1.4962x; 1.4962x over previous
#include <cuda_runtime.h>

#define B_  4
#define C_  256
#define H_  128
#define W_  128
#define HW_ (H_ * W_)
#define OH_ 256
#define OW_ 256
#define OHW_ (OH_ * OW_)
#define OFFSET_FACTOR 0.70710678118654752440f   // sqrt(128/256)

// Per-output-pixel separable bilinear metadata (shared by all 256 channels):
//   .x = wx (lerp weight along x), .y = wy, .z = bitcast(xbase | ybase<<7)
__device__ float4 g_meta[B_ * OH_ * OW_];   // 4 MB

// ---------------------------------------------------------------------------
// Kernel 1: 1x1 conv -> offsets -> separable bilinear metadata
// grid (H_, B_), block 512 = 4 channel-quarters x 128 w
// ---------------------------------------------------------------------------
__global__ __launch_bounds__(512) void offsets_kernel(const float* __restrict__ x,
                                                      const float* __restrict__ cw,   // [8][256]
                                                      const float* __restrict__ cb) { // [8]
    __shared__ float sw[256 * 8];          // weights transposed: [c][o]
    __shared__ float red[3 * 128 * 8];     // partial sums from quarters 1..3

    const int tid = threadIdx.x;
    for (int i = tid; i < 2048; i += 512) {
        int o = i >> 8, c = i & 255;
        sw[c * 8 + o] = cw[i];
    }
    __syncthreads();

    const int h = blockIdx.x;
    const int b = blockIdx.y;
    const int q = tid >> 7;      // channel quarter 0..3
    const int w = tid & 127;

    float acc[8];
#pragma unroll
    for (int o = 0; o < 8; o++) acc[o] = 0.f;

    const float* xp = x + (((long)(b * C_ + q * 64)) * H_ + h) * W_ + w;
#pragma unroll 1
    for (int t = 0; t < 8; t++) {          // 8 batches of 8 channels, MLP=8
        float v[8];
#pragma unroll
        for (int k = 0; k < 8; k++)
            v[k] = __ldg(xp + (long)(t * 8 + k) * HW_);
#pragma unroll
        for (int k = 0; k < 8; k++) {
            int c = q * 64 + t * 8 + k;
            float4 wa = *reinterpret_cast<const float4*>(&sw[c * 8]);
            float4 wb = *reinterpret_cast<const float4*>(&sw[c * 8 + 4]);
            acc[0] += wa.x * v[k]; acc[1] += wa.y * v[k];
            acc[2] += wa.z * v[k]; acc[3] += wa.w * v[k];
            acc[4] += wb.x * v[k]; acc[5] += wb.y * v[k];
            acc[6] += wb.z * v[k]; acc[7] += wb.w * v[k];
        }
    }

    if (q != 0) {
        float* r = &red[((q - 1) * 128 + w) * 8];
#pragma unroll
        for (int o = 0; o < 8; o++) r[o] = acc[o];
    }
    __syncthreads();
    if (q != 0) return;

#pragma unroll
    for (int r = 0; r < 3; r++) {
        const float* rr = &red[(r * 128 + w) * 8];
#pragma unroll
        for (int o = 0; o < 8; o++) acc[o] += rr[o];
    }
#pragma unroll
    for (int o = 0; o < 8; o++) acc[o] += cb[o];

#pragma unroll
    for (int k = 0; k < 4; k++) {
        int sy = k >> 1, sx = k & 1;
        float xc = OFFSET_FACTOR * acc[k]     + (float)w + 0.5f * (float)sx;
        float yc = OFFSET_FACTOR * acc[4 + k] + (float)h + 0.5f * (float)sy;
        float x0f = floorf(xc), y0f = floorf(yc);
        float fx = xc - x0f,   fy = yc - y0f;
        int x0 = (int)x0f, y0 = (int)y0f;

        // Fold clamping into (base, weight): taps are (base, base+1) with lerp wgt
        int   xbase; float wx;
        if (x0 < 0)            { xbase = 0;      wx = 0.f; }
        else if (x0 >= W_ - 1) { xbase = W_ - 2; wx = 1.f; }
        else                   { xbase = x0;     wx = fx;  }
        int   ybase; float wy;
        if (y0 < 0)            { ybase = 0;      wy = 0.f; }
        else if (y0 >= H_ - 1) { ybase = H_ - 2; wy = 1.f; }
        else                   { ybase = y0;     wy = fy;  }

        int pack = xbase | (ybase << 7);
        int oh = 2 * h + sy, ow = 2 * w + sx;
        g_meta[(b * OH_ + oh) * OW_ + ow] =
            make_float4(wx, wy, __int_as_float(pack), 0.f);
    }
}

// ---------------------------------------------------------------------------
// Kernel 2: bilinear gather. Pixel-outer, channel-inner (low regs, high occ).
// block 256; each block: 32x32 output tile x 16 channels
// grid (8, 8, 64)
// ---------------------------------------------------------------------------
#define CH_PER 16

__global__ __launch_bounds__(256) void gather_kernel(const float* __restrict__ x,
                                                     float* __restrict__ out) {
    const int tid = threadIdx.x;
    const int bz = blockIdx.z;
    const int b  = bz >> 4;
    const int c0 = (bz & 15) * CH_PER;
    const int oh_base = blockIdx.y * 32;
    const int ow_base = blockIdx.x * 32;

    const float* plane0 = x   + ((long)(b * C_ + c0) * HW_);
    float*       outp0  = out + ((long)(b * C_ + c0) * OHW_);

#pragma unroll 1
    for (int j = 0; j < 4; j++) {
        int p  = tid + j * 256;
        int oh = oh_base + (p >> 5);
        int ow = ow_base + (p & 31);
        float4 m = g_meta[(b * OH_ + oh) * OW_ + ow];
        float wx = m.x, wy = m.y;
        int pack  = __float_as_int(m.z);
        int otop  = ((pack >> 7) & 127) * W_ + (pack & 127);
        int obot  = otop + W_;
        int ooff  = oh * OW_ + ow;

#pragma unroll 4
        for (int cc = 0; cc < CH_PER; cc++) {
            const float* pl = plane0 + cc * HW_;
            float a = __ldg(pl + otop);
            float bb = __ldg(pl + otop + 1);
            float c = __ldg(pl + obot);
            float d = __ldg(pl + obot + 1);
            float top = fmaf(wx, bb - a, a);
            float bot = fmaf(wx, d - c, c);
            float v   = fmaf(wy, bot - top, top);
            __stcs(outp0 + (long)cc * OHW_ + ooff, v);
        }
    }
}

// ---------------------------------------------------------------------------
extern "C" void kernel_launch(void* const* d_in, const int* in_sizes, int n_in,
                              void* d_out, int out_size) {
    const float* x  = (const float*)d_in[0];  // (4,256,128,128)
    const float* cw = (const float*)d_in[1];  // (8,256,1,1)
    const float* cb = (const float*)d_in[2];  // (8,)
    float* out = (float*)d_out;               // (4,256,256,256)

    offsets_kernel<<<dim3(H_, B_), 512>>>(x, cw, cb);
    gather_kernel<<<dim3(OW_ / 32, OH_ / 32, B_ * (C_ / CH_PER)), 256>>>(x, out);
}